// round 2
// baseline (speedup 1.0000x reference)
#include <cuda_runtime.h>
#include <math.h>

// 6-layer LSTM, B=128, T=512, H=256 (input padded 128->256), FC to 10.
// Strategy: one persistent kernel per layer. Grid = 8 batch-groups x 16
// unit-groups = 128 CTAs (one per SM, residency forced by 169KB smem).
// Each CTA holds its 64-gate-row slice of W_ih AND W_hh in shared memory
// (no per-step weight traffic) and fuses the input GEMM into the scan
// (K = 256 x + 256 h per step). h is exchanged across CTAs through a
// double-buffered global array with a hand-rolled monotonic grid barrier.

#define BB   128
#define TT   512
#define HH   256
#define G4   1024   // 4*H
#define NL   6
#define COLG 16     // unit groups
#define RPB  16     // batch rows per CTA
#define UPB  16     // hidden units per CTA
#define GR   64     // gate rows per CTA (4 gates x 16 units)
#define NCTA 128
#define NTHR 256

__device__ float    g_seq[2][BB][TT][HH];  // layer ping-pong sequence buffers
__device__ float    g_hbuf[2][BB][HH];     // per-step h exchange (double buffered)
__device__ unsigned g_bar;                  // monotonic grid-barrier counter

struct SM {
  float wih[HH][GR];   // transposed: [k][j]  (conflict-free scalar loads)
  float whh[HH][GR];
  float xs[RPB][HH];   // layer-input rows for this step
  float hs[RPB][HH];   // h_{t-1} rows
  float gbuf[GR][17];  // gate pre-activations (padded vs bank conflicts)
  float cst[RPB][UPB]; // persistent cell state for this CTA's tile
  float bias[GR];      // b_ih + b_hh slice
};

__global__ void reset_bar_k() { g_bar = 0u; }

__global__ void pad_x_k(const float* __restrict__ x) {
  int idx = blockIdx.x * blockDim.x + threadIdx.x;   // over B*T*H
  int d  = idx & (HH - 1);
  int bt = idx >> 8;
  float v = (d < 128) ? x[bt * 128 + d] : 0.f;
  ((float*)g_seq)[idx] = v;   // buffer 0
}

__global__ __launch_bounds__(NTHR, 1) void lstm_scan_k(
    int layer,
    const float* __restrict__ wih_g, const float* __restrict__ whh_g,
    const float* __restrict__ bih_g, const float* __restrict__ bhh_g,
    const float* __restrict__ h0,    const float* __restrict__ c0)
{
  extern __shared__ char smraw[];
  SM* sm = (SM*)smraw;
  const int tid  = threadIdx.x;
  const int cta  = blockIdx.x;
  const int crow = cta >> 4;      // 0..7  batch group
  const int ccol = cta & 15;      // 0..15 unit group
  const int r0   = crow * RPB;
  const int u0   = ccol * UPB;

  const float* wih = wih_g + (size_t)layer * G4 * HH;
  const float* whh = whh_g + (size_t)layer * G4 * HH;

  // Load weight slices (transposed into smem). Gate-row map: j = p*16 + u,
  // global row = p*256 + u0 + u  (PyTorch gate order i,f,g,o).
  for (int idx = tid; idx < GR * HH; idx += NTHR) {
    int j = idx >> 8;       // 0..63
    int k = idx & 255;
    int u = j & 15, p = j >> 4;
    int grow = p * HH + u0 + u;
    sm->wih[k][j] = wih[(size_t)grow * HH + k];
    sm->whh[k][j] = whh[(size_t)grow * HH + k];
  }
  if (tid < GR) {
    int u = tid & 15, p = tid >> 4;
    int grow = p * HH + u0 + u;
    sm->bias[tid] = bih_g[layer * G4 + grow] + bhh_g[layer * G4 + grow];
  }
  { // cell state init (one element per thread: 16x16 = 256)
    int u = tid & 15, r = tid >> 4;
    sm->cst[r][u] = c0[((size_t)layer * BB + r0 + r) * HH + u0 + u];
  }
  __syncthreads();

  const int j     = tid & 63;   // gate row within slice
  const int rg    = tid >> 6;   // 0..3 -> 4 batch rows each
  const int rbase = rg * 4;
  const int inb   = layer & 1;
  const int outb  = inb ^ 1;
  const unsigned epbase = (unsigned)layer * TT;

  for (int t = 0; t < TT; ++t) {
    // ---- load x_t rows and h_{t-1} rows into smem (float4, coalesced) ----
    const float* hsrc = (t == 0) ? (h0 + (size_t)layer * BB * HH)
                                 : &g_hbuf[(t - 1) & 1][0][0];
    for (int idx = tid; idx < RPB * (HH / 4); idx += NTHR) {
      int r  = idx >> 6;
      int kk = idx & 63;
      ((float4*)sm->xs[r])[kk] = ((const float4*)&g_seq[inb][r0 + r][t][0])[kk];
      ((float4*)sm->hs[r])[kk] = ((const float4*)(hsrc + (size_t)(r0 + r) * HH))[kk];
    }
    __syncthreads();

    // ---- fused GEMM: g[j][r] = bias + W_ih[j,:]·x_r + W_hh[j,:]·h_r ----
    float b = sm->bias[j];
    float a0 = b, a1 = b, a2 = b, a3 = b;
    #pragma unroll 2
    for (int k = 0; k < HH; k += 4) {
      float4 x0 = *(const float4*)&sm->xs[rbase + 0][k];
      float4 x1 = *(const float4*)&sm->xs[rbase + 1][k];
      float4 x2 = *(const float4*)&sm->xs[rbase + 2][k];
      float4 x3 = *(const float4*)&sm->xs[rbase + 3][k];
      float4 h0v = *(const float4*)&sm->hs[rbase + 0][k];
      float4 h1v = *(const float4*)&sm->hs[rbase + 1][k];
      float4 h2v = *(const float4*)&sm->hs[rbase + 2][k];
      float4 h3v = *(const float4*)&sm->hs[rbase + 3][k];
      float wi, wh;
      wi = sm->wih[k + 0][j]; wh = sm->whh[k + 0][j];
      a0 += wi * x0.x + wh * h0v.x;  a1 += wi * x1.x + wh * h1v.x;
      a2 += wi * x2.x + wh * h2v.x;  a3 += wi * x3.x + wh * h3v.x;
      wi = sm->wih[k + 1][j]; wh = sm->whh[k + 1][j];
      a0 += wi * x0.y + wh * h0v.y;  a1 += wi * x1.y + wh * h1v.y;
      a2 += wi * x2.y + wh * h2v.y;  a3 += wi * x3.y + wh * h3v.y;
      wi = sm->wih[k + 2][j]; wh = sm->whh[k + 2][j];
      a0 += wi * x0.z + wh * h0v.z;  a1 += wi * x1.z + wh * h1v.z;
      a2 += wi * x2.z + wh * h2v.z;  a3 += wi * x3.z + wh * h3v.z;
      wi = sm->wih[k + 3][j]; wh = sm->whh[k + 3][j];
      a0 += wi * x0.w + wh * h0v.w;  a1 += wi * x1.w + wh * h1v.w;
      a2 += wi * x2.w + wh * h2v.w;  a3 += wi * x3.w + wh * h3v.w;
    }
    sm->gbuf[j][rbase + 0] = a0;
    sm->gbuf[j][rbase + 1] = a1;
    sm->gbuf[j][rbase + 2] = a2;
    sm->gbuf[j][rbase + 3] = a3;
    __syncthreads();

    // ---- elementwise LSTM cell: one (unit, row) per thread ----
    {
      int u = tid & 15, r = tid >> 4;
      float gi = sm->gbuf[     u][r];
      float gf = sm->gbuf[16 + u][r];
      float gg = sm->gbuf[32 + u][r];
      float go = sm->gbuf[48 + u][r];
      float cc = sm->cst[r][u];
      float si = 1.f / (1.f + expf(-gi));
      float sf = 1.f / (1.f + expf(-gf));
      float so = 1.f / (1.f + expf(-go));
      float cn = sf * cc + si * tanhf(gg);
      float hn = so * tanhf(cn);
      sm->cst[r][u] = cn;
      g_hbuf[t & 1][r0 + r][u0 + u]  = hn;   // cross-CTA exchange
      g_seq[outb][r0 + r][t][u0 + u] = hn;   // layer output
    }
    __syncthreads();

    // ---- grid barrier (monotonic epoch counter; all 128 CTAs resident) ----
    if (tid == 0) {
      __threadfence();
      atomicAdd(&g_bar, 1u);
      unsigned target = (epbase + (unsigned)t + 1u) * (unsigned)NCTA;
      while (*((volatile unsigned*)&g_bar) < target) { }
      __threadfence();
    }
    __syncthreads();
  }
}

__global__ void fc_k(const float* __restrict__ fcw, const float* __restrict__ fcb,
                     float* __restrict__ out) {
  int b    = blockIdx.x;
  int w    = threadIdx.x >> 5;   // 10 warps, one output each
  int lane = threadIdx.x & 31;
  const float* hv = &g_seq[0][b][TT - 1][0];  // after 6 layers, output is buffer 0
  const float* wr = fcw + w * HH;
  float s = 0.f;
  #pragma unroll
  for (int k = lane; k < HH; k += 32) s += hv[k] * wr[k];
  #pragma unroll
  for (int o = 16; o; o >>= 1) s += __shfl_xor_sync(0xffffffffu, s, o);
  if (lane == 0) out[b * 10 + w] = s + fcb[w];
}

extern "C" void kernel_launch(void* const* d_in, const int* in_sizes, int n_in,
                              void* d_out, int out_size) {
  (void)in_sizes; (void)n_in; (void)out_size;
  const float* x   = (const float*)d_in[0];
  const float* h0  = (const float*)d_in[1];
  const float* c0  = (const float*)d_in[2];
  const float* wih = (const float*)d_in[3];
  const float* whh = (const float*)d_in[4];
  const float* bih = (const float*)d_in[5];
  const float* bhh = (const float*)d_in[6];
  const float* fcw = (const float*)d_in[7];
  const float* fcb = (const float*)d_in[8];

  cudaFuncSetAttribute(lstm_scan_k,
                       cudaFuncAttributeMaxDynamicSharedMemorySize,
                       (int)sizeof(SM));

  reset_bar_k<<<1, 1>>>();
  pad_x_k<<<(BB * TT * HH) / NTHR, NTHR>>>(x);
  for (int l = 0; l < NL; ++l) {
    lstm_scan_k<<<NCTA, NTHR, sizeof(SM)>>>(l, wih, whh, bih, bhh, h0, c0);
  }
  fc_k<<<BB, 320>>>(fcw, fcb, (float*)d_out);
}

// round 9
// speedup vs baseline: 1.2619x; 1.2619x over previous
#include <cuda_runtime.h>
#include <math.h>

// 6-layer LSTM, B=128, T=512, H=256 (input padded 128->256), FC to 10.
// Persistent kernel per layer: 128 CTAs = 8 batch-groups x 16 unit-groups.
// Round 3 changes vs round 2:
//  - per-GROUP (16 CTA) flag sync, no atomics, no global 128-CTA barrier
//  - cp.async prefetch of x(t+1) during step t; h load overlapped with the
//    x-half of the fused GEMM
//  - packed fp32 math via fma.rn.f32x2 (2 MACs/instr), k-pair packing

#define BB   128
#define TT   512
#define HH   256
#define G4   1024
#define NL   6
#define RPB  16     // batch rows per CTA
#define UPB  16     // hidden units per CTA
#define GR   64     // gate rows per CTA (4 gates x 16 units)
#define NCTA 128
#define NTHR 256
#define PIT  258    // weight row pitch in floats (1032B: 8B-aligned, conflict-free LDS.64)

typedef unsigned long long ull;

__device__ float    g_seq[2][BB][TT][HH];  // layer ping-pong sequence buffers
__device__ float    g_hbuf[2][BB][HH];     // per-step h exchange (double buffered)
__device__ unsigned g_flags[8][32];        // per-group epoch flags (128B/group line)

struct SM {
  float wih[GR][PIT];   // [j][k], k-contiguous for paired LDS.64
  float whh[GR][PIT];
  float xs[2][RPB][HH]; // double-buffered x tiles (cp.async prefetch)
  float hs[RPB][HH];
  float gbuf[GR][17];
  float cst[RPB][UPB];
  float bias[GR];
};

__device__ __forceinline__ void cp16(void* dst, const void* src) {
  unsigned d = (unsigned)__cvta_generic_to_shared(dst);
  asm volatile("cp.async.ca.shared.global [%0], [%1], 16;" :: "r"(d), "l"(src));
}
__device__ __forceinline__ void cp_commit() { asm volatile("cp.async.commit_group;"); }
template<int N> __device__ __forceinline__ void cp_wait() {
  asm volatile("cp.async.wait_group %0;" :: "n"(N));
}

#define FMA2(acc, a, b) asm("fma.rn.f32x2 %0, %1, %2, %0;" : "+l"(acc) : "l"(a), "l"(b))

__device__ __forceinline__ ull packf2(float lo, float hi) {
  return ((ull)__float_as_uint(hi) << 32) | (ull)__float_as_uint(lo);
}
__device__ __forceinline__ float hsum(ull a) {
  return __uint_as_float((unsigned)a) + __uint_as_float((unsigned)(a >> 32));
}

__global__ void reset_flags_k() { ((unsigned*)g_flags)[threadIdx.x] = 0u; }

__global__ void pad_x_k(const float* __restrict__ x) {
  int idx = blockIdx.x * blockDim.x + threadIdx.x;   // over B*T*H
  int d  = idx & (HH - 1);
  int bt = idx >> 8;
  float v = (d < 128) ? x[bt * 128 + d] : 0.f;
  ((float*)g_seq)[idx] = v;   // buffer 0
}

__global__ __launch_bounds__(NTHR, 1) void lstm_scan_k(
    int layer,
    const float* __restrict__ wih_g, const float* __restrict__ whh_g,
    const float* __restrict__ bih_g, const float* __restrict__ bhh_g,
    const float* __restrict__ h0,    const float* __restrict__ c0)
{
  extern __shared__ char smraw[];
  SM* sm = (SM*)smraw;
  const int tid  = threadIdx.x;
  const int cta  = blockIdx.x;
  const int crow = cta >> 4;      // 0..7  batch group
  const int ccol = cta & 15;      // 0..15 unit group
  const int r0   = crow * RPB;
  const int u0   = ccol * UPB;

  const float* wih = wih_g + (size_t)layer * G4 * HH;
  const float* whh = whh_g + (size_t)layer * G4 * HH;

  // Weight slices, k-contiguous per gate row j (j = p*16+u, global row p*256+u0+u)
  for (int idx = tid; idx < GR * HH; idx += NTHR) {
    int jj = idx >> 8;
    int k  = idx & 255;
    int u = jj & 15, p = jj >> 4;
    int grow = p * HH + u0 + u;
    sm->wih[jj][k] = wih[(size_t)grow * HH + k];
    sm->whh[jj][k] = whh[(size_t)grow * HH + k];
  }
  if (tid < GR) {
    int u = tid & 15, p = tid >> 4;
    int grow = p * HH + u0 + u;
    sm->bias[tid] = bih_g[layer * G4 + grow] + bhh_g[layer * G4 + grow];
  }
  { // cell state init: one (r,u) per thread
    int u = tid & 15, r = tid >> 4;
    sm->cst[r][u] = c0[((size_t)layer * BB + r0 + r) * HH + u0 + u];
  }

  const int inb  = layer & 1;
  const int outb = inb ^ 1;
  const unsigned epbase = (unsigned)layer * TT;

  // Prologue: load xs[0] for t=0
  #pragma unroll
  for (int i = 0; i < 4; ++i) {
    int idx = tid + i * NTHR;
    int r = idx >> 6, c = idx & 63;
    cp16(&sm->xs[0][r][c * 4], &g_seq[inb][r0 + r][0][c * 4]);
  }
  cp_commit();
  cp_wait<0>();
  __syncthreads();

  const int j     = tid & 63;
  const int rbase = (tid >> 6) * 4;
  const ull* wrow_i = (const ull*)&sm->wih[j][0];
  const ull* wrow_h = (const ull*)&sm->whh[j][0];

  for (int t = 0; t < TT; ++t) {
    // ---- 1. wait for group flags >= epbase + t (h_{t-1} published) ----
    if (tid < 16) {
      unsigned tgt = epbase + (unsigned)t;
      while (*((volatile unsigned*)&g_flags[crow][tid]) < tgt) { }
      __threadfence();
    }
    __syncthreads();

    // ---- 2. async h(t) load (group H), async x(t+1) prefetch (group X) ----
    const int cb = t & 1, nb = cb ^ 1;
    {
      const float* hsrc = (t == 0) ? (h0 + (size_t)layer * BB * HH)
                                   : &g_hbuf[(t - 1) & 1][0][0];
      #pragma unroll
      for (int i = 0; i < 4; ++i) {
        int idx = tid + i * NTHR;
        int r = idx >> 6, c = idx & 63;
        cp16(&sm->hs[r][c * 4], hsrc + (size_t)(r0 + r) * HH + c * 4);
      }
      cp_commit();
      int tn = (t < TT - 1) ? t + 1 : t;   // dummy reload at t=TT-1 keeps group count fixed
      #pragma unroll
      for (int i = 0; i < 4; ++i) {
        int idx = tid + i * NTHR;
        int r = idx >> 6, c = idx & 63;
        cp16(&sm->xs[nb][r][c * 4], &g_seq[inb][r0 + r][tn][c * 4]);
      }
      cp_commit();
    }

    // ---- 3. x-half of GEMM (xs[cb] resident; overlaps h in flight) ----
    cp_wait<2>();          // ensure x prefetch from step t-1 landed
    __syncthreads();

    ull a0 = packf2(sm->bias[j], 0.f);
    ull a1 = a0, a2 = a0, a3 = a0;
    {
      const float* s0 = sm->xs[cb][rbase + 0];
      const float* s1 = sm->xs[cb][rbase + 1];
      const float* s2 = sm->xs[cb][rbase + 2];
      const float* s3 = sm->xs[cb][rbase + 3];
      #pragma unroll 4
      for (int k = 0; k < HH; k += 4) {
        ull wA = wrow_i[k >> 1];
        ull wB = wrow_i[(k >> 1) + 1];
        ulonglong2 v0 = *(const ulonglong2*)(s0 + k);
        ulonglong2 v1 = *(const ulonglong2*)(s1 + k);
        ulonglong2 v2 = *(const ulonglong2*)(s2 + k);
        ulonglong2 v3 = *(const ulonglong2*)(s3 + k);
        FMA2(a0, wA, v0.x); FMA2(a0, wB, v0.y);
        FMA2(a1, wA, v1.x); FMA2(a1, wB, v1.y);
        FMA2(a2, wA, v2.x); FMA2(a2, wB, v2.y);
        FMA2(a3, wA, v3.x); FMA2(a3, wB, v3.y);
      }
    }

    // ---- 4. h-half of GEMM ----
    cp_wait<1>();          // h(t) landed (x(t+1) may still fly)
    __syncthreads();
    {
      const float* s0 = sm->hs[rbase + 0];
      const float* s1 = sm->hs[rbase + 1];
      const float* s2 = sm->hs[rbase + 2];
      const float* s3 = sm->hs[rbase + 3];
      #pragma unroll 4
      for (int k = 0; k < HH; k += 4) {
        ull wA = wrow_h[k >> 1];
        ull wB = wrow_h[(k >> 1) + 1];
        ulonglong2 v0 = *(const ulonglong2*)(s0 + k);
        ulonglong2 v1 = *(const ulonglong2*)(s1 + k);
        ulonglong2 v2 = *(const ulonglong2*)(s2 + k);
        ulonglong2 v3 = *(const ulonglong2*)(s3 + k);
        FMA2(a0, wA, v0.x); FMA2(a0, wB, v0.y);
        FMA2(a1, wA, v1.x); FMA2(a1, wB, v1.y);
        FMA2(a2, wA, v2.x); FMA2(a2, wB, v2.y);
        FMA2(a3, wA, v3.x); FMA2(a3, wB, v3.y);
      }
    }
    sm->gbuf[j][rbase + 0] = hsum(a0);
    sm->gbuf[j][rbase + 1] = hsum(a1);
    sm->gbuf[j][rbase + 2] = hsum(a2);
    sm->gbuf[j][rbase + 3] = hsum(a3);
    __syncthreads();

    // ---- 5. elementwise LSTM cell: one (unit,row) per thread ----
    {
      int u = tid & 15, r = tid >> 4;
      float gi = sm->gbuf[     u][r];
      float gf = sm->gbuf[16 + u][r];
      float gg = sm->gbuf[32 + u][r];
      float go = sm->gbuf[48 + u][r];
      float cc = sm->cst[r][u];
      float si = 1.f / (1.f + expf(-gi));
      float sf = 1.f / (1.f + expf(-gf));
      float so = 1.f / (1.f + expf(-go));
      float cn = sf * cc + si * tanhf(gg);
      float hn = so * tanhf(cn);
      sm->cst[r][u] = cn;
      g_hbuf[t & 1][r0 + r][u0 + u]  = hn;   // group exchange
      g_seq[outb][r0 + r][t][u0 + u] = hn;   // layer output
    }
    __syncthreads();

    // ---- 6. publish epoch (sole writer of own slot, no atomics) ----
    if (tid == 0) {
      __threadfence();
      *((volatile unsigned*)&g_flags[crow][ccol]) = epbase + (unsigned)t + 1u;
    }
  }
}

__global__ void fc_k(const float* __restrict__ fcw, const float* __restrict__ fcb,
                     float* __restrict__ out) {
  int b    = blockIdx.x;
  int w    = threadIdx.x >> 5;   // 10 warps, one output each
  int lane = threadIdx.x & 31;
  const float* hv = &g_seq[0][b][TT - 1][0];  // after 6 layers, output is buffer 0
  const float* wr = fcw + w * HH;
  float s = 0.f;
  #pragma unroll
  for (int k = lane; k < HH; k += 32) s += hv[k] * wr[k];
  #pragma unroll
  for (int o = 16; o; o >>= 1) s += __shfl_xor_sync(0xffffffffu, s, o);
  if (lane == 0) out[b * 10 + w] = s + fcb[w];
}

extern "C" void kernel_launch(void* const* d_in, const int* in_sizes, int n_in,
                              void* d_out, int out_size) {
  (void)in_sizes; (void)n_in; (void)out_size;
  const float* x   = (const float*)d_in[0];
  const float* h0  = (const float*)d_in[1];
  const float* c0  = (const float*)d_in[2];
  const float* wih = (const float*)d_in[3];
  const float* whh = (const float*)d_in[4];
  const float* bih = (const float*)d_in[5];
  const float* bhh = (const float*)d_in[6];
  const float* fcw = (const float*)d_in[7];
  const float* fcb = (const float*)d_in[8];

  cudaFuncSetAttribute(lstm_scan_k,
                       cudaFuncAttributeMaxDynamicSharedMemorySize,
                       (int)sizeof(SM));

  reset_flags_k<<<1, 256>>>();
  pad_x_k<<<(BB * TT * HH) / NTHR, NTHR>>>(x);
  for (int l = 0; l < NL; ++l) {
    lstm_scan_k<<<NCTA, NTHR, sizeof(SM)>>>(l, wih, whh, bih, bhh, h0, c0);
  }
  fc_k<<<BB, 320>>>(fcw, fcb, (float*)d_out);
}